// round 13
// baseline (speedup 1.0000x reference)
#include <cuda_runtime.h>
#include <cuda_bf16.h>

// Problem constants
#define BB    4
#define NN    2048
#define DX    384
#define DQH   48
#define HH    8
#define DVH   3072   // DX * HH

// Scratch
__device__ float g_Qt[(size_t)BB * NN * DX];    // [b][tok][qglob]  (tf32-rounded)
__device__ float g_Kt[(size_t)BB * NN * DX];    // [b][tok][qglob]  (tf32-rounded)
__device__ float g_V [(size_t)BB * DVH * NN];   // [b][vglob][tok]  (tf32-rounded)
__device__ float g_Rt[(size_t)BB * NN * DVH];   // [b][tok][vglob]

// ---------------------------------------------------------------------------
// helpers
// ---------------------------------------------------------------------------
__device__ __forceinline__ unsigned f2tf32(float x) {
    unsigned r;
    asm("cvt.rna.tf32.f32 %0, %1;" : "=r"(r) : "f"(x));
    return r;
}
__device__ __forceinline__ float4 cvt4(float4 v) {
    v.x = __uint_as_float(f2tf32(v.x));
    v.y = __uint_as_float(f2tf32(v.y));
    v.z = __uint_as_float(f2tf32(v.z));
    v.w = __uint_as_float(f2tf32(v.w));
    return v;
}
__device__ __forceinline__ void mma_tf32(float& d0, float& d1, float& d2, float& d3,
                                         unsigned a0, unsigned a1, unsigned a2, unsigned a3,
                                         unsigned b0, unsigned b1) {
    asm volatile(
        "mma.sync.aligned.m16n8k8.row.col.f32.tf32.tf32.f32 "
        "{%0,%1,%2,%3}, {%4,%5,%6,%7}, {%8,%9}, {%0,%1,%2,%3};\n"
        : "+f"(d0), "+f"(d1), "+f"(d2), "+f"(d3)
        : "r"(a0), "r"(a1), "r"(a2), "r"(a3), "r"(b0), "r"(b1));
}
__device__ __forceinline__ void ldsm4(unsigned& r0, unsigned& r1, unsigned& r2, unsigned& r3,
                                      unsigned addr) {
    asm volatile("ldmatrix.sync.aligned.m8n8.x4.shared.b16 {%0,%1,%2,%3}, [%4];\n"
                 : "=r"(r0), "=r"(r1), "=r"(r2), "=r"(r3) : "r"(addr));
}
__device__ __forceinline__ void cpa16(unsigned s, const void* g) {
    asm volatile("cp.async.cg.shared.global [%0], [%1], 16;\n" :: "r"(s), "l"(g));
}
#define CP_COMMIT() asm volatile("cp.async.commit_group;\n" ::)
#define CP_WAIT(n)  asm volatile("cp.async.wait_group " #n ";\n" ::)
#define NBAR(id, cnt) asm volatile("bar.sync %0, %1;" :: "r"(id), "r"(cnt) : "memory")

// ---------------------------------------------------------------------------
// Generic tf32 GEMM + optional tf32 rounding of outputs. (unchanged, proven)
// D[m][n] = sum_k A[m][k] * B[n][k];  C addr = m*ldc_m + n*ldc_n.
// ---------------------------------------------------------------------------
__global__ __launch_bounds__(256)
void gemm_tf32(const float* __restrict__ A, const float* __restrict__ B,
               float* __restrict__ C,
               int K, int lda, int ldb,
               long sA1, long sA2, long sB1, long sB2, long sC1, long sC2,
               int ldc_m, int ldc_n, int HB, int cvt)
{
    __shared__ float As[2][128][20];
    __shared__ float Bs[2][64][20];

    const int bi = blockIdx.z;
    const int b1 = bi / HB, b2 = bi - b1 * HB;
    const float* Ap = A + b1 * sA1 + b2 * sA2;
    const float* Bp = B + b1 * sB1 + b2 * sB2;
    float* Cp = C + b1 * sC1 + b2 * sC2;

    const int m0 = blockIdx.y * 128;
    const int n0 = blockIdx.x * 64;
    const int tid = threadIdx.x;
    const int lane = tid & 31;
    const int w = tid >> 5;
    const int wm = (w >> 1) * 32;
    const int wn = (w & 1) * 32;

    const int arow = tid >> 2;
    const int aquad = (tid & 3) * 4;

    float acc[2][4][4];
#pragma unroll
    for (int mi = 0; mi < 2; mi++)
#pragma unroll
        for (int ni = 0; ni < 4; ni++)
#pragma unroll
            for (int r = 0; r < 4; r++) acc[mi][ni][r] = 0.f;

    const int ktiles = K / 16;

    float4 ra0 = *(const float4*)(Ap + (size_t)(m0 + arow) * lda + aquad);
    float4 ra1 = *(const float4*)(Ap + (size_t)(m0 + arow + 64) * lda + aquad);
    float4 rb  = *(const float4*)(Bp + (size_t)(n0 + arow) * ldb + aquad);
    *(float4*)&As[0][arow][aquad]      = cvt4(ra0);
    *(float4*)&As[0][arow + 64][aquad] = cvt4(ra1);
    *(float4*)&Bs[0][arow][aquad]      = cvt4(rb);
    __syncthreads();

    for (int kt = 0; kt < ktiles; kt++) {
        const int cur = kt & 1;
        const bool more = (kt + 1 < ktiles);
        float4 na0, na1, nb;
        if (more) {
            const int k0 = (kt + 1) * 16;
            na0 = *(const float4*)(Ap + (size_t)(m0 + arow) * lda + k0 + aquad);
            na1 = *(const float4*)(Ap + (size_t)(m0 + arow + 64) * lda + k0 + aquad);
            nb  = *(const float4*)(Bp + (size_t)(n0 + arow) * ldb + k0 + aquad);
        }

#pragma unroll
        for (int ks = 0; ks < 16; ks += 8) {
            unsigned afr[2][4], bfr[4][2];
            const int ar = wm + (lane >> 2);
            const int ac = ks + (lane & 3);
#pragma unroll
            for (int mi = 0; mi < 2; mi++) {
                afr[mi][0] = __float_as_uint(As[cur][ar + mi * 16][ac]);
                afr[mi][1] = __float_as_uint(As[cur][ar + mi * 16 + 8][ac]);
                afr[mi][2] = __float_as_uint(As[cur][ar + mi * 16][ac + 4]);
                afr[mi][3] = __float_as_uint(As[cur][ar + mi * 16 + 8][ac + 4]);
            }
#pragma unroll
            for (int ni = 0; ni < 4; ni++) {
                const int bn = wn + ni * 8 + (lane >> 2);
                bfr[ni][0] = __float_as_uint(Bs[cur][bn][ks + (lane & 3)]);
                bfr[ni][1] = __float_as_uint(Bs[cur][bn][ks + 4 + (lane & 3)]);
            }
#pragma unroll
            for (int mi = 0; mi < 2; mi++)
#pragma unroll
                for (int ni = 0; ni < 4; ni++)
                    mma_tf32(acc[mi][ni][0], acc[mi][ni][1], acc[mi][ni][2], acc[mi][ni][3],
                             afr[mi][0], afr[mi][1], afr[mi][2], afr[mi][3],
                             bfr[ni][0], bfr[ni][1]);
        }

        if (more) {
            const int nxt = cur ^ 1;
            *(float4*)&As[nxt][arow][aquad]      = cvt4(na0);
            *(float4*)&As[nxt][arow + 64][aquad] = cvt4(na1);
            *(float4*)&Bs[nxt][arow][aquad]      = cvt4(nb);
        }
        __syncthreads();
    }

#pragma unroll
    for (int mi = 0; mi < 2; mi++) {
        const int row = m0 + wm + mi * 16 + (lane >> 2);
#pragma unroll
        for (int ni = 0; ni < 4; ni++) {
            const int col = n0 + wn + ni * 8 + (lane & 3) * 2;
            float v0 = acc[mi][ni][0], v1 = acc[mi][ni][1];
            float v2 = acc[mi][ni][2], v3 = acc[mi][ni][3];
            if (cvt) {
                v0 = __uint_as_float(f2tf32(v0)); v1 = __uint_as_float(f2tf32(v1));
                v2 = __uint_as_float(f2tf32(v2)); v3 = __uint_as_float(f2tf32(v3));
            }
            Cp[(size_t)row * ldc_m + (size_t)col * ldc_n]             = v0;
            Cp[(size_t)row * ldc_m + (size_t)(col + 1) * ldc_n]       = v1;
            Cp[(size_t)(row + 8) * ldc_m + (size_t)col * ldc_n]       = v2;
            Cp[(size_t)(row + 8) * ldc_m + (size_t)(col + 1) * ldc_n] = v3;
        }
    }
}

// ---------------------------------------------------------------------------
// Fused flash attention v3: fixed-max softmax + 2-warp row-groups with
// named-barrier handoff so S/exp/PV phases of different groups overlap on
// each SMSP. Key tiles of 32; K and V double-buffered; ONE block barrier
// per tile (buffer handoff).
// Block: (b, h, 128-query tile), 512 threads (16 warps).
// Warp w: rows (w>>1)*16; S col stripe (w&1)*16; PV col stripe (w&1)*192.
// smem (floats): Qs[128][52] | Ks[2][32][52] | Ps[128][36] | Vs[2][384][36]
//                | L2r[2][128]
// ---------------------------------------------------------------------------
#define JT       32
#define NTILES   (NN / JT)
#define QS_OFF   0
#define KS_OFF   6656            // 128*52
#define KS_SZ    1664            // 32*52
#define PS_OFF   9984            // KS_OFF + 2*KS_SZ
#define VS_OFF   14592           // PS_OFF + 128*36
#define VS_SZ    13824           // 384*36
#define L2_OFF   42240           // VS_OFF + 2*VS_SZ
#define SM_FLOATS 42496          // 169984 bytes

__global__ __launch_bounds__(512)
void attn_fused(const float* __restrict__ Qt, const float* __restrict__ Kt,
                const float* __restrict__ Vg, float* __restrict__ Rt)
{
    extern __shared__ float sm[];
    const unsigned smb = (unsigned)__cvta_generic_to_shared(sm);

    const int b  = blockIdx.z;
    const int h  = blockIdx.y;
    const int i0 = blockIdx.x * 128;
    const int tid = threadIdx.x;
    const int lane = tid & 31;
    const int w = tid >> 5;

    const float* Qp = Qt + (size_t)b * NN * DX + (size_t)i0 * DX + h * DQH;
    const float* Kp = Kt + (size_t)b * NN * DX + h * DQH;
    const float* Vp = Vg + ((size_t)b * DVH + h * DX) * NN;

    const int grp = w >> 1;          // 8 groups of 2 warps (share 16 m-rows)
    const int wmS = grp * 16;        // m origin
    const int wnS = (w & 1) * 16;    // S col stripe
    const int wn  = (w & 1) * 192;   // PV col stripe

    // ---- prologue staging: Q + K0 + V0 (one cp.async group) ----
#pragma unroll
    for (int r = 0; r < 3; r++) {
        int idx = tid + r * 512;                 // < 1536
        int row = idx / 12, q = idx % 12;
        cpa16(smb + (QS_OFF + row * 52 + q * 4) * 4, Qp + (size_t)row * DX + q * 4);
    }
    if (tid < 384) {
        int row = tid / 12, q = tid % 12;
        cpa16(smb + (KS_OFF + row * 52 + q * 4) * 4, Kp + (size_t)row * DX + q * 4);
    }
#pragma unroll
    for (int r = 0; r < 6; r++) {
        int idx = tid + r * 512;                 // < 3072
        int v = idx >> 3, q = idx & 7;
        cpa16(smb + (VS_OFF + v * 36 + q * 4) * 4, Vp + (size_t)v * NN + q * 4);
    }
    CP_COMMIT();

    float acc[24][4];
#pragma unroll
    for (int ni = 0; ni < 24; ni++)
#pragma unroll
        for (int r = 0; r < 4; r++) acc[ni][r] = 0.f;

    float lpart[2];
    lpart[0] = lpart[1] = 0.f;

    const float SC = 0.14433756729740643f;   // 1/sqrt(48)

    for (int t = 0; t < NTILES; t++) {
        const int cur = t & 1;

        CP_WAIT(0);          // this thread's copies for tile t done
        __syncthreads();     // all threads' K(t)/V(t) visible; all done reading
                             // buf cur^1 (tile t-1) and all PV(t-1) reads of Ps

        // prefetch K(t+1), V(t+1) into buf cur^1 (free as of the barrier)
        if (t + 1 < NTILES) {
            const float* Kn = Kp + (size_t)(t + 1) * JT * DX;
            if (tid < 384) {
                int row = tid / 12, q = tid % 12;
                cpa16(smb + (KS_OFF + (cur ^ 1) * KS_SZ + row * 52 + q * 4) * 4,
                      Kn + (size_t)row * DX + q * 4);
            }
            const float* Vn = Vp + (size_t)(t + 1) * JT;
#pragma unroll
            for (int r = 0; r < 6; r++) {
                int idx = tid + r * 512;
                int v = idx >> 3, q = idx & 7;
                cpa16(smb + (VS_OFF + (cur ^ 1) * VS_SZ + v * 36 + q * 4) * 4,
                      Vn + (size_t)v * NN + q * 4);
            }
            CP_COMMIT();
        }

        // ---- S = Q K^T : m16 x n16 x k48 per warp ----
        float sacc[2][4];
#pragma unroll
        for (int ni = 0; ni < 2; ni++)
#pragma unroll
            for (int r = 0; r < 4; r++) sacc[ni][r] = 0.f;

#pragma unroll
        for (int ks = 0; ks < 6; ks++) {
            unsigned b0, b1, b2, b3;
            {
                int row = wnS + ((lane >> 4) & 1) * 8 + (lane & 7);
                int col = ks * 8 + ((lane >> 3) & 1) * 4;
                ldsm4(b0, b1, b2, b3,
                      smb + (KS_OFF + cur * KS_SZ + row * 52 + col) * 4);
            }
            unsigned a0, a1, a2, a3;
            {
                int row = wmS + (lane & 15);
                int col = ks * 8 + (lane >> 4) * 4;
                ldsm4(a0, a1, a2, a3, smb + (QS_OFF + row * 52 + col) * 4);
            }
            mma_tf32(sacc[0][0], sacc[0][1], sacc[0][2], sacc[0][3],
                     a0, a1, a2, a3, b0, b1);
            mma_tf32(sacc[1][0], sacc[1][1], sacc[1][2], sacc[1][3],
                     a0, a1, a2, a3, b2, b3);
        }

        // exp on registers, accumulate l, store P patch (tf32-rounded)
        {
            int r0 = wmS + (lane >> 2);
#pragma unroll
            for (int ni = 0; ni < 2; ni++) {
                int c0 = wnS + ni * 8 + (lane & 3) * 2;
                float e0 = __uint_as_float(f2tf32(__expf(sacc[ni][0] * SC)));
                float e1 = __uint_as_float(f2tf32(__expf(sacc[ni][1] * SC)));
                float e2 = __uint_as_float(f2tf32(__expf(sacc[ni][2] * SC)));
                float e3 = __uint_as_float(f2tf32(__expf(sacc[ni][3] * SC)));
                lpart[0] += e0 + e1;
                lpart[1] += e2 + e3;
                *(float2*)&sm[PS_OFF + r0 * 36 + c0]       = make_float2(e0, e1);
                *(float2*)&sm[PS_OFF + (r0 + 8) * 36 + c0] = make_float2(e2, e3);
            }
        }

        // group-local handoff: both warps of this group finished their P patch
        NBAR(1 + grp, 64);

        // ---- PV: O += P V : m16 x n192 x k32 per warp ----
#pragma unroll
        for (int ks = 0; ks < 4; ks++) {
            unsigned a0, a1, a2, a3;
            {
                int row = wmS + (lane & 15);
                int col = ks * 8 + (lane >> 4) * 4;
                ldsm4(a0, a1, a2, a3, smb + (PS_OFF + row * 36 + col) * 4);
            }
#pragma unroll
            for (int nip = 0; nip < 12; nip++) {
                unsigned q0, q1, q2, q3;
                int row = wn + nip * 16 + ((lane >> 4) & 1) * 8 + (lane & 7);
                int col = ks * 8 + ((lane >> 3) & 1) * 4;
                ldsm4(q0, q1, q2, q3,
                      smb + (VS_OFF + cur * VS_SZ + row * 36 + col) * 4);
                mma_tf32(acc[2 * nip][0], acc[2 * nip][1],
                         acc[2 * nip][2], acc[2 * nip][3],
                         a0, a1, a2, a3, q0, q1);
                mma_tf32(acc[2 * nip + 1][0], acc[2 * nip + 1][1],
                         acc[2 * nip + 1][2], acc[2 * nip + 1][3],
                         a0, a1, a2, a3, q2, q3);
            }
        }
        // next iteration's __syncthreads covers: Ps rewrite safety and
        // V/K buffer reuse. Groups drift freely until then.
    }

    // ---- final l reduction: quad shuffles, 2 col-stripe slots ----
#pragma unroll
    for (int hh = 0; hh < 2; hh++) {
        lpart[hh] += __shfl_xor_sync(0xffffffffu, lpart[hh], 1);
        lpart[hh] += __shfl_xor_sync(0xffffffffu, lpart[hh], 2);
    }
    if ((lane & 3) == 0) {
        int r = lane >> 2;
        sm[L2_OFF + (w & 1) * 128 + wmS + r]     = lpart[0];
        sm[L2_OFF + (w & 1) * 128 + wmS + 8 + r] = lpart[1];
    }
    __syncthreads();

    // ---- epilogue: divide by l, store Rt[b][i0+row][h*384 + col] ----
    float* Rp = Rt + ((size_t)b * NN + i0) * DVH + h * DX;
    {
        int r0 = wmS + (lane >> 2);
        float la = sm[L2_OFF + r0] + sm[L2_OFF + 128 + r0];
        float lb = sm[L2_OFF + r0 + 8] + sm[L2_OFF + 128 + r0 + 8];
        float ia = 1.f / la;
        float ib = 1.f / lb;
#pragma unroll
        for (int ni = 0; ni < 24; ni++) {
            int c0 = wn + ni * 8 + (lane & 3) * 2;
            *(float2*)(Rp + (size_t)r0 * DVH + c0) =
                make_float2(acc[ni][0] * ia, acc[ni][1] * ia);
            *(float2*)(Rp + (size_t)(r0 + 8) * DVH + c0) =
                make_float2(acc[ni][2] * ib, acc[ni][3] * ib);
        }
    }
}

// ---------------------------------------------------------------------------
extern "C" void kernel_launch(void* const* d_in, const int* in_sizes, int n_in,
                              void* d_out, int out_size)
{
    const float* X   = (const float*)d_in[0];
    const float* W_q = (const float*)d_in[1];
    const float* W_k = (const float*)d_in[2];
    const float* W_v = (const float*)d_in[3];
    const float* W_r = (const float*)d_in[4];
    float* out = (float*)d_out;

    float *gQt, *gKt, *gV, *gRt;
    cudaGetSymbolAddress((void**)&gQt, g_Qt);
    cudaGetSymbolAddress((void**)&gKt, g_Kt);
    cudaGetSymbolAddress((void**)&gV,  g_V);
    cudaGetSymbolAddress((void**)&gRt, g_Rt);

    static int smem_set = 0;
    if (!smem_set) {
        cudaFuncSetAttribute(attn_fused, cudaFuncAttributeMaxDynamicSharedMemorySize,
                             SM_FLOATS * 4);
        smem_set = 1;
    }

    const dim3 blk(256);

    // Q projection -> g_Qt[b][tok][qglob], tf32-rounded
    gemm_tf32<<<dim3(NN / 64, DX / 128, BB), blk>>>(
        W_q, X, gQt, DX, DX, DX,
        0, 0, (long)NN * DX, 0, (long)NN * DX, 0,
        1, DX, 1, 1);
    // K projection -> g_Kt
    gemm_tf32<<<dim3(NN / 64, DX / 128, BB), blk>>>(
        W_k, X, gKt, DX, DX, DX,
        0, 0, (long)NN * DX, 0, (long)NN * DX, 0,
        1, DX, 1, 1);
    // V projection -> g_V[b][vglob][tok] (m-major), tf32-rounded
    gemm_tf32<<<dim3(NN / 64, DVH / 128, BB), blk>>>(
        W_v, X, gV, DX, DX, DX,
        0, 0, (long)NN * DX, 0, (long)DVH * NN, 0,
        NN, 1, 1, 1);

    // fused attention -> g_Rt[b][tok][vglob]
    attn_fused<<<dim3(NN / 128, HH, BB), dim3(512), SM_FLOATS * 4>>>(gQt, gKt, gV, gRt);

    // output projection -> out[b][tok][d]
    gemm_tf32<<<dim3(NN / 64, DX / 128, BB), blk>>>(
        W_r, gRt, out, DVH, DVH, DVH,
        0, 0, (long)NN * DVH, 0, (long)NN * DX, 0,
        1, DX, 1, 0);
}